// round 9
// baseline (speedup 1.0000x reference)
#include <cuda_runtime.h>
#include <cuda_fp16.h>
#include <math.h>
#include <stdint.h>

#define BATCH   8192
#define DIM     256
#define KRED    1024
#define NCOEF   5
#define NLAYERS 2
#define LN_EPS  1e-6f

// ---------------------------------------------------------------------------
// Scratch
// ---------------------------------------------------------------------------
__device__ float  g_h [BATCH * DIM];
__device__ __half g_Bn[NLAYERS * DIM * KRED];
__device__ float  g_bias[NLAYERS * DIM];

// ---------------------------------------------------------------------------
// Helpers
// ---------------------------------------------------------------------------
__device__ __forceinline__ uint32_t smem_u32(const void* p) {
    uint32_t a;
    asm("{ .reg .u64 t; cvta.to.shared.u64 t, %1; cvt.u32.u64 %0, t; }"
        : "=r"(a) : "l"(p));
    return a;
}
__device__ __forceinline__ void mma_f16_16n8k16(float* d, const uint32_t* a,
                                                const uint32_t* b) {
    asm volatile(
        "mma.sync.aligned.m16n8k16.row.col.f32.f16.f16.f32 "
        "{%0,%1,%2,%3}, {%4,%5,%6,%7}, {%8,%9}, {%0,%1,%2,%3};"
        : "+f"(d[0]), "+f"(d[1]), "+f"(d[2]), "+f"(d[3])
        : "r"(a[0]), "r"(a[1]), "r"(a[2]), "r"(a[3]),
          "r"(b[0]), "r"(b[1]));
}
#define LDSM4(r0, r1, r2, r3, addr) \
    asm volatile("ldmatrix.sync.aligned.m8n8.x4.shared.b16 {%0,%1,%2,%3}, [%4];" \
        : "=r"(r0), "=r"(r1), "=r"(r2), "=r"(r3) : "r"(addr))
#define CP_ASYNC16(dst, src) \
    asm volatile("cp.async.ca.shared.global [%0], [%1], 16;" \
        :: "r"(dst), "l"(src))
#define CP_COMMIT()  asm volatile("cp.async.commit_group;" ::: "memory")
#define CP_WAIT1()   asm volatile("cp.async.wait_group 1;"  ::: "memory")
#define BAR_SYNC(id)   asm volatile("bar.sync %0, 384;"   :: "r"(id) : "memory")
#define BAR_ARRIVE(id) asm volatile("bar.arrive %0, 384;" :: "r"(id) : "memory")
#define FENCE_CTA()    asm volatile("fence.acq_rel.cta;"  ::: "memory")

// barrier ids: FULL0=1, FULL1=2 (A buf ready), FREE0=3, FREE1=4 (A consumed)

// ---------------------------------------------------------------------------
// build Bn[l][o][k], k = i*4 + (c-1), fp16
// ---------------------------------------------------------------------------
__global__ void build_Bn(const float* __restrict__ coefs,
                         __half* __restrict__ Bn) {
    int idx = blockIdx.x * blockDim.x + threadIdx.x;
    const int total = NLAYERS * DIM * KRED;
    if (idx >= total) return;
    int k = idx & (KRED - 1);
    int o = (idx >> 10) & (DIM - 1);
    int l = idx >> 18;
    int i = k >> 2;
    int c = (k & 3) + 1;
    Bn[idx] = __float2half_rn(
        coefs[(((size_t)(l * DIM + i)) * DIM + o) * NCOEF + c]);
}

// ---------------------------------------------------------------------------
// bias[l][o] = sum_i coefs[l][i][o][0]  (exact fp32)
// ---------------------------------------------------------------------------
__global__ void __launch_bounds__(128)
build_bias(const float* __restrict__ coefs, float* __restrict__ bias) {
    int lo = blockIdx.x;
    int l = lo >> 8, o = lo & 255;
    float s = 0.0f;
    for (int i = threadIdx.x; i < DIM; i += 128)
        s += coefs[(((size_t)(l * DIM + i)) * DIM + o) * NCOEF];
    #pragma unroll
    for (int off = 16; off; off >>= 1) s += __shfl_xor_sync(0xFFFFFFFFu, s, off);
    __shared__ float red[4];
    if ((threadIdx.x & 31) == 0) red[threadIdx.x >> 5] = s;
    __syncthreads();
    if (threadIdx.x == 0)
        bias[lo] = red[0] + red[1] + red[2] + red[3];
}

// ---------------------------------------------------------------------------
// Warp-specialized fused layer.
// CTA tile 128x128, BK=64, 384 threads:
//   warps 0-7 : consumers, 64x32 warp tiles (2m x 4n), frag double-buffer
//   warps 8-11: producers (LDG h -> LN -> tanh -> Jacobi -> STS A tile)
// ---------------------------------------------------------------------------
#define BK        64
#define NCHUNK    (KRED / BK)         // 16
#define ROWB      144
#define A_TILE_B  (128 * ROWB)        // 18432
#define B_TILE_B  (128 * ROWB)        // 18432
#define SM_A      1024
#define SM_B      (1024 + 2 * A_TILE_B)
#define SMEM_FUSED_BYTES (1024 + 2 * A_TILE_B + 3 * B_TILE_B)  // 93184

__global__ void __launch_bounds__(384, 1)
fused_layer(const float* __restrict__ h,
            const __half* __restrict__ Bn,
            const float* __restrict__ biasP0,
            const float* __restrict__ lnscale,
            const float* __restrict__ lnbias,
            const float* __restrict__ alphas,
            int layer,
            float* __restrict__ C) {
    extern __shared__ char sm[];
    const uint32_t sb = smem_u32(sm);
    float2* stats = (float2*)sm;

    const int tid = threadIdx.x;
    const int lid = tid & 31;
    const int wid = tid >> 5;

    const int bm = blockIdx.x * 128;
    const int bn = blockIdx.y * 128;

    // Jacobi scalar coefficients
    const float a = tanhf(alphas[layer]);
    float bb[3], cc[3];
    #pragma unroll
    for (int k = 2; k <= 4; k++) {
        float kf = (float)k;
        float t  = 2.0f * kf + 2.0f * a;
        float A  = 2.0f * kf * (kf + 2.0f * a) * (t - 2.0f);
        float B  = (t - 1.0f) * t * (t - 2.0f);
        float Cc = 2.0f * (kf + a - 1.0f) * (kf + a - 1.0f) * t;
        float invA = 1.0f / A;
        bb[k - 2] = B * invA;
        cc[k - 2] = Cc * invA;
    }
    const float p1c = a + 1.0f;

    // B stage loader (consumers: 256 threads, 1024 x 16B tasks)
    auto issueB = [&](int stage, int ch) {
        const uint32_t st = sb + SM_B + (uint32_t)stage * B_TILE_B;
        #pragma unroll
        for (int it = 0; it < 4; it++) {
            int idx = tid + it * 256;
            int row = idx >> 3, q8 = idx & 7;
            const __half* gb = Bn + (size_t)(bn + row) * KRED + ch * BK + q8 * 8;
            CP_ASYNC16(st + row * ROWB + q8 * 16, gb);
        }
        CP_COMMIT();
    };

    // ---------------- prologue: B pipeline + LN stats -----------------------
    if (wid < 8) {
        issueB(0, 0);
        issueB(1, 1);
        #pragma unroll 1
        for (int j = 0; j < 16; j++) {
            int row = wid * 16 + j;
            const float4* p = (const float4*)(h + (size_t)(bm + row) * DIM) + lid * 2;
            float4 u = p[0], v = p[1];
            float s  = u.x + u.y + u.z + u.w + v.x + v.y + v.z + v.w;
            float s2 = u.x*u.x + u.y*u.y + u.z*u.z + u.w*u.w
                     + v.x*v.x + v.y*v.y + v.z*v.z + v.w*v.w;
            #pragma unroll
            for (int off = 16; off; off >>= 1) {
                s  += __shfl_xor_sync(0xFFFFFFFFu, s,  off);
                s2 += __shfl_xor_sync(0xFFFFFFFFu, s2, off);
            }
            if (lid == 0) {
                float mu  = s * (1.0f / DIM);
                float var = s2 * (1.0f / DIM) - mu * mu;
                stats[row] = make_float2(mu, rsqrtf(var + LN_EPS));
            }
        }
    }
    __syncthreads();

    if (wid >= 8) {
        // ================= PRODUCER PATH (128 threads, row = p) =============
        const int p = tid - 256;
        const float2 st = stats[p];
        const float mu = st.x, rs = st.y;
        const float* hrow = h + (size_t)(bm + p) * DIM;

        #pragma unroll 1
        for (int ch = 0; ch < NCHUNK; ch++) {
            float4 hv[4];
            #pragma unroll
            for (int j = 0; j < 4; j++)
                hv[j] = *(const float4*)(hrow + ch * 16 + j * 4);
            float4 scv[4], biv[4];
            #pragma unroll
            for (int j = 0; j < 4; j++) {
                scv[j] = *(const float4*)(lnscale + ch * 16 + j * 4);
                biv[j] = *(const float4*)(lnbias  + ch * 16 + j * 4);
            }

            if (ch >= 2) BAR_SYNC(3 + (ch & 1));   // wait A buf free

            char* abase = sm + SM_A + (ch & 1) * A_TILE_B + p * ROWB;
            #pragma unroll
            for (int j = 0; j < 4; j++) {
                float xv[4] = {hv[j].x, hv[j].y, hv[j].z, hv[j].w};
                float sc[4] = {scv[j].x, scv[j].y, scv[j].z, scv[j].w};
                float bi[4] = {biv[j].x, biv[j].y, biv[j].z, biv[j].w};
                uint32_t oh[8];
                #pragma unroll
                for (int e = 0; e < 4; e++) {
                    float x  = tanhf((xv[e] - mu) * rs * sc[e] + bi[e]);
                    float P1 = p1c * x;
                    float P2 = bb[0] * x * P1 - cc[0];
                    float P3 = bb[1] * x * P2 - cc[1] * P1;
                    float P4 = bb[2] * x * P3 - cc[2] * P2;
                    __half2 h0 = __floats2half2_rn(P1, P2);
                    __half2 h1 = __floats2half2_rn(P3, P4);
                    oh[2 * e]     = *(uint32_t*)&h0;
                    oh[2 * e + 1] = *(uint32_t*)&h1;
                }
                uint4* dst = (uint4*)(abase + j * 32);
                dst[0] = make_uint4(oh[0], oh[1], oh[2], oh[3]);
                dst[1] = make_uint4(oh[4], oh[5], oh[6], oh[7]);
            }
            FENCE_CTA();
            BAR_ARRIVE(1 + (ch & 1));              // A(ch) full
        }
    } else {
        // ================= CONSUMER PATH (256 threads, 8 warps) =============
        const int warp_m = wid & 1;       // 64 rows
        const int warp_n = wid >> 1;      // 32 cols
        const int qr = lid >> 2;
        const int qc = lid & 3;

        const uint32_t a_loff =
            (uint32_t)((warp_m * 64 + (lid & 15)) * ROWB + ((lid >> 4) << 4));
        const uint32_t b_loff =
            (uint32_t)((warp_n * 32 + ((lid & 7) | ((lid >> 4) << 3))) * ROWB +
                       (((lid >> 3) & 1) << 4));

        float acc[4][4][4];
        #pragma unroll
        for (int mt = 0; mt < 4; mt++)
            #pragma unroll
            for (int nt = 0; nt < 4; nt++)
                #pragma unroll
                for (int j = 0; j < 4; j++) acc[mt][nt][j] = 0.0f;

        uint32_t af[2][4][4], bf[2][4][2];

        #pragma unroll 1
        for (int c = 0; c < NCHUNK; c++) {
            CP_WAIT1();                 // B(c) landed
            BAR_SYNC(1 + (c & 1));      // A(c) full

            if (c + 2 < NCHUNK) issueB((c + 2) % 3, c + 2);
            else CP_COMMIT();

            const uint32_t stA = sb + SM_A + (uint32_t)(c & 1) * A_TILE_B;
            const uint32_t stB = sb + SM_B + (uint32_t)(c % 3) * B_TILE_B;

            // preload ks=0 fragments
            #pragma unroll
            for (int mt = 0; mt < 4; mt++)
                LDSM4(af[0][mt][0], af[0][mt][1], af[0][mt][2], af[0][mt][3],
                      stA + a_loff + (uint32_t)(mt * 16 * ROWB));
            #pragma unroll
            for (int p2 = 0; p2 < 2; p2++)
                LDSM4(bf[0][2*p2][0], bf[0][2*p2][1],
                      bf[0][2*p2+1][0], bf[0][2*p2+1][1],
                      stB + b_loff + (uint32_t)(p2 * 16 * ROWB));

            #pragma unroll
            for (int ks = 0; ks < 4; ks++) {
                const int cur = ks & 1;
                if (ks < 3) {
                    const int nxt = cur ^ 1;
                    #pragma unroll
                    for (int mt = 0; mt < 4; mt++)
                        LDSM4(af[nxt][mt][0], af[nxt][mt][1],
                              af[nxt][mt][2], af[nxt][mt][3],
                              stA + a_loff +
                              (uint32_t)(mt * 16 * ROWB + (ks + 1) * 32));
                    #pragma unroll
                    for (int p2 = 0; p2 < 2; p2++)
                        LDSM4(bf[nxt][2*p2][0], bf[nxt][2*p2][1],
                              bf[nxt][2*p2+1][0], bf[nxt][2*p2+1][1],
                              stB + b_loff +
                              (uint32_t)(p2 * 16 * ROWB + (ks + 1) * 32));
                }
                #pragma unroll
                for (int mt = 0; mt < 4; mt++)
                    #pragma unroll
                    for (int nt = 0; nt < 4; nt++)
                        mma_f16_16n8k16(acc[mt][nt], af[cur][mt], bf[cur][nt]);
            }

            if (c + 2 < NCHUNK) BAR_ARRIVE(3 + (c & 1));   // A(c) consumed
        }

        // epilogue: C = (acc + bias) / DIM
        const float inv = 1.0f / (float)DIM;
        const int re = bm + warp_m * 64 + qr;
        const int ce = bn + warp_n * 32 + qc * 2;
        #pragma unroll
        for (int mt = 0; mt < 4; mt++) {
            #pragma unroll
            for (int nt = 0; nt < 4; nt++) {
                int col = ce + nt * 8;
                float2 bv = *(const float2*)(biasP0 + col);
                int row = re + mt * 16;
                float2 o0, o1;
                o0.x = (acc[mt][nt][0] + bv.x) * inv;
                o0.y = (acc[mt][nt][1] + bv.y) * inv;
                o1.x = (acc[mt][nt][2] + bv.x) * inv;
                o1.y = (acc[mt][nt][3] + bv.y) * inv;
                *(float2*)(C + (size_t)row * DIM + col)       = o0;
                *(float2*)(C + (size_t)(row + 8) * DIM + col) = o1;
            }
        }
    }
}

// ---------------------------------------------------------------------------
// Launch
// ---------------------------------------------------------------------------
extern "C" void kernel_launch(void* const* d_in, const int* in_sizes, int n_in,
                              void* d_out, int out_size) {
    const float* x        = (const float*)d_in[0];
    const float* coefs    = (const float*)d_in[1];
    const float* alphas   = (const float*)d_in[2];
    const float* ln_scale = (const float*)d_in[3];
    const float* ln_bias  = (const float*)d_in[4];
    float* out = (float*)d_out;

    float* hbuf; cudaGetSymbolAddress((void**)&hbuf, g_h);
    __half* Bn;  cudaGetSymbolAddress((void**)&Bn,   g_Bn);
    float* bias; cudaGetSymbolAddress((void**)&bias, g_bias);

    cudaFuncSetAttribute(fused_layer,
                         cudaFuncAttributeMaxDynamicSharedMemorySize,
                         SMEM_FUSED_BYTES);

    {
        int total = NLAYERS * DIM * KRED;
        build_Bn<<<(total + 255) / 256, 256>>>(coefs, Bn);
        build_bias<<<NLAYERS * DIM, 128>>>(coefs, bias);
    }

    dim3 ggrid(BATCH / 128, DIM / 128);   // (64, 2)

    fused_layer<<<ggrid, 384, SMEM_FUSED_BYTES>>>(
        x, Bn, bias, ln_scale, ln_bias, alphas, 0, hbuf);

    fused_layer<<<ggrid, 384, SMEM_FUSED_BYTES>>>(
        hbuf, Bn + (size_t)DIM * KRED, bias + DIM,
        ln_scale + DIM, ln_bias + DIM, alphas, 1, out);
}

// round 10
// speedup vs baseline: 1.0687x; 1.0687x over previous
#include <cuda_runtime.h>
#include <cuda_fp16.h>
#include <math.h>
#include <stdint.h>

#define BATCH   8192
#define DIM     256
#define KRED    1024
#define NCOEF   5
#define NLAYERS 2
#define LN_EPS  1e-6f

// ---------------------------------------------------------------------------
// Scratch
// ---------------------------------------------------------------------------
__device__ float  g_h [BATCH * DIM];
__device__ __half g_Bn[NLAYERS * DIM * KRED];
__device__ float  g_bias[NLAYERS * DIM];

// ---------------------------------------------------------------------------
// Helpers
// ---------------------------------------------------------------------------
__device__ __forceinline__ uint32_t smem_u32(const void* p) {
    uint32_t a;
    asm("{ .reg .u64 t; cvta.to.shared.u64 t, %1; cvt.u32.u64 %0, t; }"
        : "=r"(a) : "l"(p));
    return a;
}
__device__ __forceinline__ void mma_f16_16n8k16(float* d, const uint32_t* a,
                                                const uint32_t* b) {
    asm volatile(
        "mma.sync.aligned.m16n8k16.row.col.f32.f16.f16.f32 "
        "{%0,%1,%2,%3}, {%4,%5,%6,%7}, {%8,%9}, {%0,%1,%2,%3};"
        : "+f"(d[0]), "+f"(d[1]), "+f"(d[2]), "+f"(d[3])
        : "r"(a[0]), "r"(a[1]), "r"(a[2]), "r"(a[3]),
          "r"(b[0]), "r"(b[1]));
}
#define LDSM4(r0, r1, r2, r3, addr) \
    asm volatile("ldmatrix.sync.aligned.m8n8.x4.shared.b16 {%0,%1,%2,%3}, [%4];" \
        : "=r"(r0), "=r"(r1), "=r"(r2), "=r"(r3) : "r"(addr))
#define CP_ASYNC16(dst, src) \
    asm volatile("cp.async.ca.shared.global [%0], [%1], 16;" \
        :: "r"(dst), "l"(src))
#define CP_COMMIT()  asm volatile("cp.async.commit_group;" ::: "memory")
#define CP_WAIT1()   asm volatile("cp.async.wait_group 1;"  ::: "memory")

// ---------------------------------------------------------------------------
// build Bn[l][o][k], k = i*4 + (c-1), fp16
// ---------------------------------------------------------------------------
__global__ void build_Bn(const float* __restrict__ coefs,
                         __half* __restrict__ Bn) {
    int idx = blockIdx.x * blockDim.x + threadIdx.x;
    const int total = NLAYERS * DIM * KRED;
    if (idx >= total) return;
    int k = idx & (KRED - 1);
    int o = (idx >> 10) & (DIM - 1);
    int l = idx >> 18;
    int i = k >> 2;
    int c = (k & 3) + 1;
    Bn[idx] = __float2half_rn(
        coefs[(((size_t)(l * DIM + i)) * DIM + o) * NCOEF + c]);
}

// ---------------------------------------------------------------------------
// bias[l][o] = sum_i coefs[l][i][o][0]  (exact fp32)
// ---------------------------------------------------------------------------
__global__ void __launch_bounds__(128)
build_bias(const float* __restrict__ coefs, float* __restrict__ bias) {
    int lo = blockIdx.x;
    int l = lo >> 8, o = lo & 255;
    float s = 0.0f;
    for (int i = threadIdx.x; i < DIM; i += 128)
        s += coefs[(((size_t)(l * DIM + i)) * DIM + o) * NCOEF];
    #pragma unroll
    for (int off = 16; off; off >>= 1) s += __shfl_xor_sync(0xFFFFFFFFu, s, off);
    __shared__ float red[4];
    if ((threadIdx.x & 31) == 0) red[threadIdx.x >> 5] = s;
    __syncthreads();
    if (threadIdx.x == 0)
        bias[lo] = red[0] + red[1] + red[2] + red[3];
}

// ---------------------------------------------------------------------------
// Fused layer: LN + tanh + Jacobi A-gen + fp16 HMMA GEMM.
// CTA tile 64(M) x 128(N), BK=64, 256 threads, 8 warps (2m x 4n, 32x32 tiles).
// 73 KB smem, <=128 regs -> 2 CTAs/SM co-resident to hide gen/sync bubbles.
// ---------------------------------------------------------------------------
#define BK        64
#define NCHUNK    (KRED / BK)         // 16
#define ROWB      144
#define A_TILE_B  (64 * ROWB)         // 9216
#define B_TILE_B  (128 * ROWB)        // 18432
#define SM_A      1024                // 2 buffers
#define SM_B      (1024 + 2 * A_TILE_B)   // 19456, 3 stages
#define SMEM_FUSED_BYTES (1024 + 2 * A_TILE_B + 3 * B_TILE_B)  // 74752

__global__ void __launch_bounds__(256, 2)
fused_layer(const float* __restrict__ h,
            const __half* __restrict__ Bn,
            const float* __restrict__ biasP0,
            const float* __restrict__ lnscale,
            const float* __restrict__ lnbias,
            const float* __restrict__ alphas,
            int layer,
            float* __restrict__ C) {
    extern __shared__ char sm[];
    const uint32_t sb = smem_u32(sm);
    float2* stats = (float2*)sm;      // 64 rows

    const int tid = threadIdx.x;
    const int lid = tid & 31;
    const int wid = tid >> 5;
    const int warp_m = wid & 1;       // 32 rows
    const int warp_n = wid >> 1;      // 32 cols
    const int qr = lid >> 2;
    const int qc = lid & 3;

    const int bm = blockIdx.x * 64;
    const int bn = blockIdx.y * 128;

    // Jacobi scalar coefficients
    const float a = tanhf(alphas[layer]);
    float bb[3], cc[3];
    #pragma unroll
    for (int k = 2; k <= 4; k++) {
        float kf = (float)k;
        float t  = 2.0f * kf + 2.0f * a;
        float A  = 2.0f * kf * (kf + 2.0f * a) * (t - 2.0f);
        float B  = (t - 1.0f) * t * (t - 2.0f);
        float Cc = 2.0f * (kf + a - 1.0f) * (kf + a - 1.0f) * t;
        float invA = 1.0f / A;
        bb[k - 2] = B * invA;
        cc[k - 2] = Cc * invA;
    }
    const float p1c = a + 1.0f;

    // B stage loader: 128 rows x 8 x 16B = 1024 tasks / 256 threads
    auto issueB = [&](int stage, int ch) {
        const uint32_t st = sb + SM_B + (uint32_t)stage * B_TILE_B;
        #pragma unroll
        for (int it = 0; it < 4; it++) {
            int idx = tid + it * 256;
            int row = idx >> 3, q8 = idx & 7;
            const __half* gb = Bn + (size_t)(bn + row) * KRED + ch * BK + q8 * 8;
            CP_ASYNC16(st + row * ROWB + q8 * 16, gb);
        }
        CP_COMMIT();
    };

    // h register prefetch: thread -> row tid>>2 (0..63), float4 col (tid&3)*4
    const int i4 = tid & 3;
    const int r0 = tid >> 2;
    auto loadH = [&](int ch, float4& v) {
        v = *(const float4*)(h + (size_t)(bm + r0) * DIM + ch * 16 + i4 * 4);
    };

    // A generation: row r0, 4 input cols -> 16 halves (32 B)
    auto genA = [&](int ch, int abuf, float4 v) {
        float4 sc = *(const float4*)(lnscale + ch * 16 + i4 * 4);
        float4 bi = *(const float4*)(lnbias  + ch * 16 + i4 * 4);
        float2 st = stats[r0];
        float xv[4] = {v.x, v.y, v.z, v.w};
        float scv[4] = {sc.x, sc.y, sc.z, sc.w};
        float biv[4] = {bi.x, bi.y, bi.z, bi.w};
        uint32_t oh[8];
        #pragma unroll
        for (int e = 0; e < 4; e++) {
            float x  = tanhf((xv[e] - st.x) * st.y * scv[e] + biv[e]);
            float P1 = p1c * x;
            float P2 = bb[0] * x * P1 - cc[0];
            float P3 = bb[1] * x * P2 - cc[1] * P1;
            float P4 = bb[2] * x * P3 - cc[2] * P2;
            __half2 h0 = __floats2half2_rn(P1, P2);
            __half2 h1 = __floats2half2_rn(P3, P4);
            oh[2 * e]     = *(uint32_t*)&h0;
            oh[2 * e + 1] = *(uint32_t*)&h1;
        }
        uint4* dst = (uint4*)(sm + SM_A + abuf * A_TILE_B + r0 * ROWB + i4 * 32);
        dst[0] = make_uint4(oh[0], oh[1], oh[2], oh[3]);
        dst[1] = make_uint4(oh[4], oh[5], oh[6], oh[7]);
    };

    // -------- prologue ------------------------------------------------------
    issueB(0, 0);
    issueB(1, 1);

    {   // LN stats: warp w -> rows w*8 .. w*8+7
        #pragma unroll 1
        for (int j = 0; j < 8; j++) {
            int row = wid * 8 + j;
            const float4* p = (const float4*)(h + (size_t)(bm + row) * DIM) + lid * 2;
            float4 u = p[0], v = p[1];
            float s  = u.x + u.y + u.z + u.w + v.x + v.y + v.z + v.w;
            float s2 = u.x*u.x + u.y*u.y + u.z*u.z + u.w*u.w
                     + v.x*v.x + v.y*v.y + v.z*v.z + v.w*v.w;
            #pragma unroll
            for (int off = 16; off; off >>= 1) {
                s  += __shfl_xor_sync(0xFFFFFFFFu, s,  off);
                s2 += __shfl_xor_sync(0xFFFFFFFFu, s2, off);
            }
            if (lid == 0) {
                float mu  = s * (1.0f / DIM);
                float var = s2 * (1.0f / DIM) - mu * mu;
                stats[row] = make_float2(mu, rsqrtf(var + LN_EPS));
            }
        }
    }
    __syncthreads();              // stats visible

    float4 hc, hn;
    loadH(0, hc);
    genA(0, 0, hc);
    loadH(1, hn);

    CP_WAIT1();                   // B(0) arrived
    __syncthreads();              // A(0) + B(0) visible

    // ldmatrix lane offsets
    const uint32_t a_loff =
        (uint32_t)((warp_m * 32 + (lid & 15)) * ROWB + ((lid >> 4) << 4));
    const uint32_t b_loff =
        (uint32_t)((warp_n * 32 + ((lid & 7) | ((lid >> 4) << 3))) * ROWB +
                   (((lid >> 3) & 1) << 4));

    float acc[2][4][4];
    #pragma unroll
    for (int mt = 0; mt < 2; mt++)
        #pragma unroll
        for (int nt = 0; nt < 4; nt++)
            #pragma unroll
            for (int j = 0; j < 4; j++) acc[mt][nt][j] = 0.0f;

    #pragma unroll 1
    for (int c = 0; c < NCHUNK; c++) {
        if (c + 2 < NCHUNK) issueB((c + 2) % 3, c + 2);
        else CP_COMMIT();

        const uint32_t stA = sb + SM_A + (uint32_t)(c & 1) * A_TILE_B;
        const uint32_t stB = sb + SM_B + (uint32_t)(c % 3) * B_TILE_B;

        #pragma unroll
        for (int ks = 0; ks < 4; ks++) {
            uint32_t af[2][4], bf[4][2];
            #pragma unroll
            for (int mt = 0; mt < 2; mt++)
                LDSM4(af[mt][0], af[mt][1], af[mt][2], af[mt][3],
                      stA + a_loff + (uint32_t)(mt * 16 * ROWB + ks * 32));
            #pragma unroll
            for (int p = 0; p < 2; p++)
                LDSM4(bf[2*p][0], bf[2*p][1], bf[2*p+1][0], bf[2*p+1][1],
                      stB + b_loff + (uint32_t)(p * 16 * ROWB + ks * 32));
            #pragma unroll
            for (int mt = 0; mt < 2; mt++)
                #pragma unroll
                for (int nt = 0; nt < 4; nt++)
                    mma_f16_16n8k16(acc[mt][nt], af[mt], bf[nt]);
        }

        if (c + 1 < NCHUNK) {
            genA(c + 1, (c + 1) & 1, hn);
            if (c + 2 < NCHUNK) loadH(c + 2, hn);
            CP_WAIT1();           // B(c+1) arrived
            __syncthreads();      // A(c+1) + B(c+1) visible
        }
    }

    // -------- epilogue: C = (acc + bias) / DIM ------------------------------
    const float inv = 1.0f / (float)DIM;
    const int re = bm + warp_m * 32 + qr;
    const int ce = bn + warp_n * 32 + qc * 2;
    #pragma unroll
    for (int mt = 0; mt < 2; mt++) {
        #pragma unroll
        for (int nt = 0; nt < 4; nt++) {
            int col = ce + nt * 8;
            float2 bv = *(const float2*)(biasP0 + col);
            int row = re + mt * 16;
            float2 o0, o1;
            o0.x = (acc[mt][nt][0] + bv.x) * inv;
            o0.y = (acc[mt][nt][1] + bv.y) * inv;
            o1.x = (acc[mt][nt][2] + bv.x) * inv;
            o1.y = (acc[mt][nt][3] + bv.y) * inv;
            *(float2*)(C + (size_t)row * DIM + col)       = o0;
            *(float2*)(C + (size_t)(row + 8) * DIM + col) = o1;
        }
    }
}

// ---------------------------------------------------------------------------
// Launch
// ---------------------------------------------------------------------------
extern "C" void kernel_launch(void* const* d_in, const int* in_sizes, int n_in,
                              void* d_out, int out_size) {
    const float* x        = (const float*)d_in[0];
    const float* coefs    = (const float*)d_in[1];
    const float* alphas   = (const float*)d_in[2];
    const float* ln_scale = (const float*)d_in[3];
    const float* ln_bias  = (const float*)d_in[4];
    float* out = (float*)d_out;

    float* hbuf; cudaGetSymbolAddress((void**)&hbuf, g_h);
    __half* Bn;  cudaGetSymbolAddress((void**)&Bn,   g_Bn);
    float* bias; cudaGetSymbolAddress((void**)&bias, g_bias);

    cudaFuncSetAttribute(fused_layer,
                         cudaFuncAttributeMaxDynamicSharedMemorySize,
                         SMEM_FUSED_BYTES);

    {
        int total = NLAYERS * DIM * KRED;
        build_Bn<<<(total + 255) / 256, 256>>>(coefs, Bn);
        build_bias<<<NLAYERS * DIM, 128>>>(coefs, bias);
    }

    dim3 ggrid(BATCH / 64, DIM / 128);   // (128, 2) = 256 CTAs

    fused_layer<<<ggrid, 256, SMEM_FUSED_BYTES>>>(
        x, Bn, bias, ln_scale, ln_bias, alphas, 0, hbuf);

    fused_layer<<<ggrid, 256, SMEM_FUSED_BYTES>>>(
        hbuf, Bn + (size_t)DIM * KRED, bias + DIM,
        ln_scale + DIM, ln_bias + DIM, alphas, 1, out);
}